// round 4
// baseline (speedup 1.0000x reference)
#include <cuda_runtime.h>
#include <math.h>

#define DM 96
#define DI 192
#define DSN 16
#define RK 6
#define BB 2
#define LL 4096
#define CC 192
#define LT 4288
#define NC 32
#define CL 134

// ---------------- static scratch (no allocs allowed) ----------------
__device__ __align__(16) float  g_wtA[DM * 2 * DI];   // in_proj_w transposed: [k][j] 96x384
__device__ __align__(16) float  g_wtO[DI * DM];       // out_proj_w transposed: [d][o] 192x96
__device__ __align__(16) float  g_An [DI * DSN];      // -exp(A_logs)
__device__ __align__(16) float  g_x1 [BB * DI * LL];  // conv input  (b,c,h,w)
__device__ __align__(16) float  g_xs [BB * DI * LT];  // u = xs      (b,d,ltot)
__device__ __align__(16) float  g_z  [BB * LL * DI];  // z           (b,l,d)
__device__ __align__(16) float  g_dxc[BB * DI * 1024];// stride-2 conv out (b,c,1024)
__device__ __align__(16) float2 g_bc [BB * LT * DSN]; // (B_n, C_n)  (b,l,n)
__device__ __align__(16) float2 g_q2 [BB * DI * LT];  // (delta*log2e, delta*u)
__device__ __align__(16) float  g_yt [BB * LL * DI];  // scan y (b,l,d)
__device__ __align__(16) float  g_hend[BB * DI * NC * DSN];
__device__ __align__(16) float  g_P   [BB * DI * NC * DSN];
__device__ __align__(16) float  g_h0  [BB * DI * NC * DSN];

__device__ __forceinline__ float ex2(float x) {
    float r; asm("ex2.approx.ftz.f32 %0, %1;" : "=f"(r) : "f"(x)); return r;
}
__device__ __forceinline__ float silu_f(float v) {
    return __fdividef(v, 1.f + __expf(-v));
}

// ---------------- K0: weight transposes + A table ----------------
__global__ void k0_prep(const float* __restrict__ ipw, const float* __restrict__ opw,
                        const float* __restrict__ alogs) {
    int t = blockIdx.x * blockDim.x + threadIdx.x;
    if (t < 2 * DI * DM) {
        int j = t / DM, k = t % DM;
        g_wtA[k * (2 * DI) + j] = ipw[t];
    }
    if (t < DM * DI) {
        int o = t / DI, d = t % DI;
        g_wtO[d * DM + o] = opw[t];
    }
    if (t < DI * DSN) {
        g_An[t] = -expf(alogs[t]);
    }
}

// ---------------- K1: xz = x @ in_proj_w.T ; split x1 (NCHW) / z (b,l,d) ----------------
__global__ void __launch_bounds__(384) k1_inproj(const float* __restrict__ x) {
    __shared__ __align__(16) float xt[96 * 36];
    __shared__ __align__(16) float zs[32 * DI];
    int b  = blockIdx.y;
    int l0 = blockIdx.x * 32;
    int tid = threadIdx.x;

    const float4* xin = (const float4*)(x + ((size_t)b * LL + l0) * DM);
    for (int i = tid; i < 32 * 24; i += 384) {
        float4 v = xin[i];
        int l = i / 24, k4 = (i % 24) * 4;
        xt[(k4 + 0) * 36 + l] = v.x;
        xt[(k4 + 1) * 36 + l] = v.y;
        xt[(k4 + 2) * 36 + l] = v.z;
        xt[(k4 + 3) * 36 + l] = v.w;
    }
    __syncthreads();

    int j = tid;
    float acc[32];
#pragma unroll
    for (int l = 0; l < 32; l++) acc[l] = 0.f;
    for (int k = 0; k < 96; k++) {
        float w = g_wtA[k * 384 + j];
#pragma unroll
        for (int l4 = 0; l4 < 8; l4++) {
            float4 xv = *(const float4*)&xt[k * 36 + l4 * 4];
            acc[l4 * 4 + 0] += xv.x * w;
            acc[l4 * 4 + 1] += xv.y * w;
            acc[l4 * 4 + 2] += xv.z * w;
            acc[l4 * 4 + 3] += xv.w * w;
        }
    }
    if (j < DI) {
        float* dst = g_x1 + ((size_t)b * DI + j) * LL + l0;
#pragma unroll
        for (int l4 = 0; l4 < 8; l4++) {
            *(float4*)(dst + l4 * 4) =
                make_float4(acc[l4*4], acc[l4*4+1], acc[l4*4+2], acc[l4*4+3]);
        }
    } else {
        int d = j - DI;
#pragma unroll
        for (int l = 0; l < 32; l++) zs[l * DI + d] = acc[l];
    }
    __syncthreads();
    float4* zdst = (float4*)(g_z + ((size_t)b * LL + l0) * DI);
    const float4* zsrc = (const float4*)zs;
    for (int i = tid; i < 32 * 48; i += 384) zdst[i] = zsrc[i];
}

// ---------------- K23: fused depthwise conv s1+SiLU and conv s2 (smem-resident) ----------------
__global__ void __launch_bounds__(256) k23_conv(const float* __restrict__ cw1,
                                                const float* __restrict__ cb1,
                                                const float* __restrict__ cw2,
                                                const float* __restrict__ cb2) {
    __shared__ __align__(16) float s_in [64 * 64];
    __shared__ __align__(16) float s_mid[64 * 64];
    __shared__ float w1[9], w2[9], bb1, bb2;
    int plane = blockIdx.x;              // b*DI + c
    int c = plane % DI;
    int tid = threadIdx.x;
    if (tid < 9)        w1[tid]     = cw1[c * 9 + tid];
    else if (tid < 18)  w2[tid - 9] = cw2[c * 9 + tid - 9];
    else if (tid == 18) bb1 = cb1[c];
    else if (tid == 19) bb2 = cb2[c];

    const float4* src = (const float4*)(g_x1 + (size_t)plane * LL);
    float4* s4 = (float4*)s_in;
#pragma unroll
    for (int i = 0; i < 4; i++) s4[tid + 256 * i] = src[tid + 256 * i];
    __syncthreads();

    // conv1 (s1, p1) + SiLU: thread = column w, quarter q of rows
    int w = tid & 63, q = tid >> 6;
    float* dst1 = g_xs + (size_t)plane * LT + CC;
    int wl = (w > 0) ? -1 : 0, wr = (w < 63) ? 1 : 0;
#pragma unroll 4
    for (int r = 0; r < 16; r++) {
        int h = q * 16 + r;
        float s = bb1;
#pragma unroll
        for (int kh = 0; kh < 3; kh++) {
            int ih = h + kh - 1;
            if (ih < 0 || ih >= 64) continue;
            const float* row = s_in + ih * 64 + w;
            float acc = w1[kh * 3 + 1] * row[0];
            if (wl) acc += w1[kh * 3 + 0] * row[-1];
            if (wr) acc += w1[kh * 3 + 2] * row[1];
            s += acc;
        }
        float v = silu_f(s);
        s_mid[h * 64 + w] = v;
        dst1[h * 64 + w] = v;
    }
    __syncthreads();

    // conv2 (s2, p1): thread = ow column, 4 rows each
    int ow = tid & 31;
    int oq = tid >> 5;                   // 0..7
    float* dst2 = g_dxc + (size_t)plane * 1024;
#pragma unroll
    for (int r = 0; r < 4; r++) {
        int oh = oq * 4 + r;
        float s = bb2;
#pragma unroll
        for (int kh = 0; kh < 3; kh++) {
            int ih = 2 * oh + kh - 1;
            if (ih < 0 || ih >= 64) continue;
#pragma unroll
            for (int kw = 0; kw < 3; kw++) {
                int iw = 2 * ow + kw - 1;
                if (iw < 0 || iw >= 64) continue;
                s += w2[kh * 3 + kw] * s_mid[ih * 64 + iw];
            }
        }
        dst2[oh * 32 + ow] = s;
    }
}

// ---------------- K4: depth_fc + bias + SiLU (tiled, K-split, coalesced) ----------------
__global__ void __launch_bounds__(384) k4_fc(const float* __restrict__ wfc,
                                             const float* __restrict__ fcb) {
    __shared__ __align__(16) float sW[2][192 * 20];
    __shared__ __align__(16) float sX[2][8 * 16];
    __shared__ __align__(16) float sred[192 * 8];
    int b   = blockIdx.y;
    int lp0 = blockIdx.x * 8;
    int tid = threadIdx.x;
    int d   = tid % 192;
    int kh  = tid / 192;

    float acc[8];
#pragma unroll
    for (int r = 0; r < 8; r++) acc[r] = 0.f;

    for (int ch = 0; ch < 32; ch++) {
        int k0 = kh * 512 + ch * 16;
        __syncthreads();
#pragma unroll
        for (int j = 0; j < 4; j++) {
            int qd = d + 192 * j;
            int row = qd >> 2, col = qd & 3;
            float4 v = *(const float4*)(wfc + (size_t)row * 1024 + k0 + col * 4);
            *(float4*)&sW[kh][row * 20 + col * 4] = v;
        }
        if (d < 32) {
            int row = d >> 2, col = d & 3;
            float4 v = *(const float4*)(g_dxc + ((size_t)b * DI + lp0 + row) * 1024 + k0 + col * 4);
            *(float4*)&sX[kh][row * 16 + col * 4] = v;
        }
        __syncthreads();
#pragma unroll
        for (int j4 = 0; j4 < 4; j4++) {
            float4 wv = *(const float4*)&sW[kh][d * 20 + j4 * 4];
#pragma unroll
            for (int r = 0; r < 8; r++) {
                float4 xv = *(const float4*)&sX[kh][r * 16 + j4 * 4];
                acc[r] += wv.x * xv.x + wv.y * xv.y + wv.z * xv.z + wv.w * xv.w;
            }
        }
    }
    __syncthreads();
    if (kh == 0) {
#pragma unroll
        for (int r = 0; r < 8; r++) sred[d * 8 + r] = acc[r];
    }
    __syncthreads();
    if (kh == 1) {
        float bv = fcb[d];
        float o[8];
#pragma unroll
        for (int r = 0; r < 8; r++) o[r] = silu_f(acc[r] + sred[d * 8 + r] + bv);
        float* dst = g_xs + ((size_t)b * DI + d) * LT + lp0;
        *(float4*)dst       = make_float4(o[0], o[1], o[2], o[3]);
        *(float4*)(dst + 4) = make_float4(o[4], o[5], o[6], o[7]);
    }
}

// ---------------- K5: x_proj + dt proj + softplus precompute (tiled) ----------------
__global__ void __launch_bounds__(256) k5_xproj(const float* __restrict__ xpw,
                                                const float* __restrict__ dtw,
                                                const float* __restrict__ dtb,
                                                const float* __restrict__ dsv) {
    __shared__ __align__(16) float s_xp[38 * 193];
    __shared__ __align__(16) float sxd[38 * 36];
    __shared__ __align__(16) float s_dtw[DI * RK];
    __shared__ float s_dtb[DI];
    __shared__ float s_ds[DI];
    int tid = threadIdx.x;
    int b   = blockIdx.y;
    int l0  = blockIdx.x * 32;

    for (int i = tid; i < 38 * DI; i += 256) s_xp[(i / DI) * 193 + (i % DI)] = xpw[i];
    for (int i = tid; i < DI * RK; i += 256) s_dtw[i] = dtw[i];
    for (int i = tid; i < DI; i += 256) { s_dtb[i] = dtb[i]; s_ds[i] = dsv[i]; }
    __syncthreads();

    const float* ub = g_xs + (size_t)b * DI * LT + l0;
    for (int item = tid; item < 38 * 8; item += 256) {
        int c = item >> 3, lq = item & 7;
        float4 acc = make_float4(0.f, 0.f, 0.f, 0.f);
        const float* xr = s_xp + c * 193;
#pragma unroll 4
        for (int d = 0; d < DI; d++) {
            float xp = xr[d];
            float4 uv = *(const float4*)(ub + (size_t)d * LT + lq * 4);
            acc.x += xp * uv.x; acc.y += xp * uv.y;
            acc.z += xp * uv.z; acc.w += xp * uv.w;
        }
        *(float4*)&sxd[c * 36 + lq * 4] = acc;
    }
    __syncthreads();

    {
        int n = tid & 15;
        int lh = tid >> 4;
#pragma unroll
        for (int rr = 0; rr < 2; rr++) {
            int l = lh + rr * 16;
            g_bc[((size_t)b * LT + l0 + l) * DSN + n] =
                make_float2(sxd[(RK + n) * 36 + l], sxd[(RK + DSN + n) * 36 + l]);
        }
    }

    const float L2E = 1.4426950408889634f;
    for (int item = tid; item < DI * 8; item += 256) {
        int d = item >> 3, lq = item & 7;
        float dt0 = s_dtb[d], dt1 = dt0, dt2 = dt0, dt3 = dt0;
#pragma unroll
        for (int r = 0; r < RK; r++) {
            float w = s_dtw[d * RK + r];
            float4 xv = *(const float4*)&sxd[r * 36 + lq * 4];
            dt0 += w * xv.x; dt1 += w * xv.y; dt2 += w * xv.z; dt3 += w * xv.w;
        }
        float del[4]; float dts[4] = {dt0, dt1, dt2, dt3};
#pragma unroll
        for (int j = 0; j < 4; j++) {
            float dt = dts[j];
            if (dt > 20.f)       del[j] = dt;
            else if (dt < -20.f) del[j] = __expf(dt);
            else                 del[j] = log1pf(__expf(dt));
        }
        float4 uv = *(const float4*)(ub + (size_t)d * LT + lq * 4);
        float2* qd = g_q2 + ((size_t)b * DI + d) * LT + l0 + lq * 4;
        *(float4*)qd       = make_float4(del[0] * L2E, del[0] * uv.x, del[1] * L2E, del[1] * uv.y);
        *(float4*)(qd + 2) = make_float4(del[2] * L2E, del[2] * uv.z, del[3] * L2E, del[3] * uv.w);
    }
}

// ---------------- K6: chunked selective scan (2 states per thread) ----------------
// warp layout: lane = half*16 + n; warp covers d0..d0+3 (thread owns d0+half, d0+half+2)
__global__ void __launch_bounds__(128) k6_phaseA() {
    int W    = blockIdx.x * 4 + (threadIdx.x >> 5);
    int lane = threadIdx.x & 31;
    int grp  = W >> 5;                   // 0..95 = b*48 + dq
    int c    = W & 31;
    int half = lane >> 4;
    int n    = lane & 15;
    int b  = grp / 48, dq = grp % 48;
    int d_a = dq * 4 + half, d_b = d_a + 2;
    int g_a = b * DI + d_a, g_b = b * DI + d_b;
    float An_a = g_An[d_a * DSN + n];
    float An_b = g_An[d_b * DSN + n];
    const float2* qa = g_q2 + (size_t)g_a * LT;
    const float2* qb = g_q2 + (size_t)g_b * LT;
    const float2* bc = g_bc + (size_t)b * LT * DSN;
    float ha = 0.f, Pa = 1.f, hb = 0.f, Pb = 1.f;
    int l0 = c * CL;
#pragma unroll 2
    for (int l = l0; l < l0 + CL; l++) {
        float2 q1 = qa[l];
        float2 q2v = qb[l];
        float2 bv = bc[(size_t)l * DSN + n];
        float aa = ex2(q1.x * An_a);
        float ab = ex2(q2v.x * An_b);
        Pa *= aa; ha = aa * ha + q1.y * bv.x;
        Pb *= ab; hb = ab * hb + q2v.y * bv.x;
    }
    int ia = (g_a * NC + c) * DSN + n;
    int ib = (g_b * NC + c) * DSN + n;
    g_hend[ia] = ha; g_P[ia] = Pa;
    g_hend[ib] = hb; g_P[ib] = Pb;
}

__global__ void k6_phaseB() {
    int t = blockIdx.x * blockDim.x + threadIdx.x;
    if (t >= BB * DI * DSN) return;
    int n = t & 15;
    int g = t >> 4;
    float h = 0.f;
    for (int c = 0; c < NC; c++) {
        int idx = (g * NC + c) * DSN + n;
        g_h0[idx] = h;
        h = g_P[idx] * h + g_hend[idx];
    }
}

__global__ void __launch_bounds__(128) k6_phaseC(const float* __restrict__ dsv) {
    int W    = blockIdx.x * 4 + (threadIdx.x >> 5);
    int lane = threadIdx.x & 31;
    int grp  = W >> 5;
    int c    = W & 31;
    int half = lane >> 4;
    int n    = lane & 15;
    int b  = grp / 48, dq = grp % 48;
    int d_a = dq * 4 + half, d_b = d_a + 2;
    int g_a = b * DI + d_a, g_b = b * DI + d_b;
    float An_a = g_An[d_a * DSN + n];
    float An_b = g_An[d_b * DSN + n];
    float ds_a = dsv[d_a], ds_b = dsv[d_b];
    const float2* qa = g_q2 + (size_t)g_a * LT;
    const float2* qb = g_q2 + (size_t)g_b * LT;
    const float*  ua = g_xs + (size_t)g_a * LT;
    const float*  ub = g_xs + (size_t)g_b * LT;
    const float2* bc = g_bc + (size_t)b * LT * DSN;
    float ha = g_h0[(g_a * NC + c) * DSN + n];
    float hb = g_h0[(g_b * NC + c) * DSN + n];
    int l0 = c * CL;
#pragma unroll 2
    for (int l = l0; l < l0 + CL; l++) {
        float2 q1 = qa[l];
        float2 q2v = qb[l];
        float2 bv = bc[(size_t)l * DSN + n];
        float aa = ex2(q1.x * An_a);
        float ab = ex2(q2v.x * An_b);
        ha = aa * ha + q1.y * bv.x;
        hb = ab * hb + q2v.y * bv.x;
        float pa = ha * bv.y;
        float pb = hb * bv.y;
        pa += __shfl_xor_sync(0xffffffffu, pa, 1);
        pb += __shfl_xor_sync(0xffffffffu, pb, 1);
        pa += __shfl_xor_sync(0xffffffffu, pa, 2);
        pb += __shfl_xor_sync(0xffffffffu, pb, 2);
        pa += __shfl_xor_sync(0xffffffffu, pa, 4);
        pb += __shfl_xor_sync(0xffffffffu, pb, 4);
        pa += __shfl_xor_sync(0xffffffffu, pa, 8);
        pb += __shfl_xor_sync(0xffffffffu, pb, 8);
        if (n == 0 && l >= CC) {
            float* yo = g_yt + ((size_t)b * LL + (l - CC)) * DI;
            yo[d_a] = pa + ds_a * ua[l];
            yo[d_b] = pb + ds_b * ub[l];
        }
    }
}

// ---------------- K7: LayerNorm + SiLU(z) gate + out_proj (8 l per block) ----------------
__global__ void __launch_bounds__(192) k7_out(const float* __restrict__ onw,
                                              const float* __restrict__ onb,
                                              float* __restrict__ out) {
    __shared__ __align__(16) float sy [8 * DI];
    __shared__ __align__(16) float sgv[8 * DI];
    __shared__ __align__(16) float sred[8 * DM];
    __shared__ float smu[8], srs[8];
    int b   = blockIdx.y;
    int l0  = blockIdx.x * 8;
    int tid = threadIdx.x;
    int lane = tid & 31, w = tid >> 5;

    const float4* ysrc = (const float4*)(g_yt + ((size_t)b * LL + l0) * DI);
    float4* syd = (float4*)sy;
#pragma unroll
    for (int i = 0; i < 2; i++) syd[tid + 192 * i] = ysrc[tid + 192 * i];
    __syncthreads();

#pragma unroll
    for (int pass = 0; pass < 2; pass++) {
        int l = pass * 6 + w;
        if (l < 8) {
            float s1 = 0.f, s2 = 0.f;
#pragma unroll
            for (int k = 0; k < 6; k++) {
                float v = sy[l * DI + lane + 32 * k];
                s1 += v; s2 += v * v;
            }
#pragma unroll
            for (int o = 16; o > 0; o >>= 1) {
                s1 += __shfl_xor_sync(0xffffffffu, s1, o);
                s2 += __shfl_xor_sync(0xffffffffu, s2, o);
            }
            if (lane == 0) {
                float mu = s1 * (1.f / 192.f);
                smu[l] = mu;
                srs[l] = rsqrtf(s2 * (1.f / 192.f) - mu * mu + 1e-5f);
            }
        }
    }
    __syncthreads();

    float wn = onw[tid], bn = onb[tid];
    const float* zr = g_z + ((size_t)b * LL + l0) * DI + tid;
#pragma unroll
    for (int l = 0; l < 8; l++) {
        float y  = sy[l * DI + tid];
        float yn = (y - smu[l]) * srs[l] * wn + bn;
        float zv = zr[(size_t)l * DI];
        sgv[l * DI + tid] = yn * silu_f(zv);
    }
    __syncthreads();

    int o = tid % DM, half = tid / DM, d0 = half * DM;
    float acc[8];
#pragma unroll
    for (int l = 0; l < 8; l++) acc[l] = 0.f;
    const float* wp = g_wtO + (size_t)d0 * DM + o;
#pragma unroll 4
    for (int i = 0; i < 96; i++) {
        float wv = wp[(size_t)i * DM];
        const float* gv = sgv + d0 + i;
#pragma unroll
        for (int l = 0; l < 8; l++) acc[l] += gv[l * DI] * wv;
    }
    if (half == 0) {
#pragma unroll
        for (int l = 0; l < 8; l++) sred[l * DM + o] = acc[l];
    }
    __syncthreads();
    if (half == 1) {
        float* op = out + ((size_t)b * LL + l0) * DM + o;
#pragma unroll
        for (int l = 0; l < 8; l++) op[(size_t)l * DM] = acc[l] + sred[l * DM + o];
    }
}

// ---------------- launch ----------------
extern "C" void kernel_launch(void* const* d_in, const int* in_sizes, int n_in,
                              void* d_out, int out_size) {
    const float* x            = (const float*)d_in[0];
    const float* in_proj_w    = (const float*)d_in[1];
    const float* conv2d_w     = (const float*)d_in[2];
    const float* conv2d_b     = (const float*)d_in[3];
    const float* depth_conv_w = (const float*)d_in[4];
    const float* depth_conv_b = (const float*)d_in[5];
    const float* depth_fc_w   = (const float*)d_in[6];
    const float* depth_fc_b   = (const float*)d_in[7];
    const float* x_proj_w     = (const float*)d_in[8];
    const float* dt_projs_w   = (const float*)d_in[9];
    const float* dt_projs_b   = (const float*)d_in[10];
    const float* A_logs       = (const float*)d_in[11];
    const float* Ds           = (const float*)d_in[12];
    const float* out_norm_w   = (const float*)d_in[13];
    const float* out_norm_b   = (const float*)d_in[14];
    const float* out_proj_w   = (const float*)d_in[15];
    float* out = (float*)d_out;

    k0_prep<<<(2 * DI * DM + 255) / 256, 256>>>(in_proj_w, out_proj_w, A_logs);
    k1_inproj<<<dim3(LL / 32, BB), 384>>>(x);
    k23_conv<<<BB * DI, 256>>>(conv2d_w, conv2d_b, depth_conv_w, depth_conv_b);
    k4_fc<<<dim3(24, BB), 384>>>(depth_fc_w, depth_fc_b);
    k5_xproj<<<dim3(LT / 32, BB), 256>>>(x_proj_w, dt_projs_w, dt_projs_b, Ds);
    k6_phaseA<<<768, 128>>>();
    k6_phaseB<<<24, 256>>>();
    k6_phaseC<<<768, 128>>>(Ds);
    k7_out<<<dim3(LL / 8, BB), 192>>>(out_norm_w, out_norm_b, out);
}

// round 5
// speedup vs baseline: 1.1465x; 1.1465x over previous
#include <cuda_runtime.h>
#include <math.h>

#define DM 96
#define DI 192
#define DSN 16
#define RK 6
#define BB 2
#define LL 4096
#define CC 192
#define LT 4288
#define NC 32
#define CL 134
#define KSPLIT 16
#define KCHUNK 64
#define MTILE 16

// ---------------- static scratch (no allocs allowed) ----------------
__device__ __align__(16) float  g_wtA[DM * 2 * DI];   // in_proj_w transposed: [k][j] 96x384
__device__ __align__(16) float  g_wtO[DI * DM];       // out_proj_w transposed: [d][o] 192x96
__device__ __align__(16) float  g_An [DI * DSN];      // -exp(A_logs)
__device__ __align__(16) float  g_x1 [BB * DI * LL];  // conv input  (b,c,h,w)
__device__ __align__(16) float  g_xs [BB * DI * LT];  // u = xs      (b,d,ltot)
__device__ __align__(16) float  g_z  [BB * LL * DI];  // z           (b,l,d)
__device__ __align__(16) float  g_dxc[BB * DI * 1024];// stride-2 conv out (b,c,1024)
__device__ __align__(16) float  g_fcp[KSPLIT * BB * DI * DI]; // depth_fc partials [ks][m][d]
__device__ __align__(16) float2 g_bc [BB * LT * DSN]; // (B_n, C_n)  (b,l,n)
__device__ __align__(16) float2 g_q2 [BB * DI * LT];  // (delta*log2e, delta*u)
__device__ __align__(16) float  g_yt [BB * LL * DI];  // scan y (b,l,d)
__device__ __align__(16) float  g_hend[BB * DI * NC * DSN];
__device__ __align__(16) float  g_P   [BB * DI * NC * DSN];
__device__ __align__(16) float  g_h0  [BB * DI * NC * DSN];

__device__ __forceinline__ float ex2(float x) {
    float r; asm("ex2.approx.ftz.f32 %0, %1;" : "=f"(r) : "f"(x)); return r;
}
__device__ __forceinline__ float silu_f(float v) {
    return __fdividef(v, 1.f + __expf(-v));
}

// ---------------- K0: weight transposes + A table ----------------
__global__ void k0_prep(const float* __restrict__ ipw, const float* __restrict__ opw,
                        const float* __restrict__ alogs) {
    int t = blockIdx.x * blockDim.x + threadIdx.x;
    if (t < 2 * DI * DM) {
        int j = t / DM, k = t % DM;
        g_wtA[k * (2 * DI) + j] = ipw[t];
    }
    if (t < DM * DI) {
        int o = t / DI, d = t % DI;
        g_wtO[d * DM + o] = opw[t];
    }
    if (t < DI * DSN) {
        g_An[t] = -expf(alogs[t]);
    }
}

// ---------------- K1: xz = x @ in_proj_w.T ; split x1 (NCHW) / z (b,l,d) ----------------
__global__ void __launch_bounds__(384) k1_inproj(const float* __restrict__ x) {
    __shared__ __align__(16) float xt[96 * 36];
    __shared__ __align__(16) float zs[32 * DI];
    int b  = blockIdx.y;
    int l0 = blockIdx.x * 32;
    int tid = threadIdx.x;

    const float4* xin = (const float4*)(x + ((size_t)b * LL + l0) * DM);
    for (int i = tid; i < 32 * 24; i += 384) {
        float4 v = xin[i];
        int l = i / 24, k4 = (i % 24) * 4;
        xt[(k4 + 0) * 36 + l] = v.x;
        xt[(k4 + 1) * 36 + l] = v.y;
        xt[(k4 + 2) * 36 + l] = v.z;
        xt[(k4 + 3) * 36 + l] = v.w;
    }
    __syncthreads();

    int j = tid;
    float acc[32];
#pragma unroll
    for (int l = 0; l < 32; l++) acc[l] = 0.f;
    for (int k = 0; k < 96; k++) {
        float w = g_wtA[k * 384 + j];
#pragma unroll
        for (int l4 = 0; l4 < 8; l4++) {
            float4 xv = *(const float4*)&xt[k * 36 + l4 * 4];
            acc[l4 * 4 + 0] += xv.x * w;
            acc[l4 * 4 + 1] += xv.y * w;
            acc[l4 * 4 + 2] += xv.z * w;
            acc[l4 * 4 + 3] += xv.w * w;
        }
    }
    if (j < DI) {
        float* dst = g_x1 + ((size_t)b * DI + j) * LL + l0;
#pragma unroll
        for (int l4 = 0; l4 < 8; l4++) {
            *(float4*)(dst + l4 * 4) =
                make_float4(acc[l4*4], acc[l4*4+1], acc[l4*4+2], acc[l4*4+3]);
        }
    } else {
        int d = j - DI;
#pragma unroll
        for (int l = 0; l < 32; l++) zs[l * DI + d] = acc[l];
    }
    __syncthreads();
    float4* zdst = (float4*)(g_z + ((size_t)b * LL + l0) * DI);
    const float4* zsrc = (const float4*)zs;
    for (int i = tid; i < 32 * 48; i += 384) zdst[i] = zsrc[i];
}

// ---------------- K23: fused depthwise conv s1+SiLU and conv s2 (smem-resident) ----------------
__global__ void __launch_bounds__(256) k23_conv(const float* __restrict__ cw1,
                                                const float* __restrict__ cb1,
                                                const float* __restrict__ cw2,
                                                const float* __restrict__ cb2) {
    __shared__ __align__(16) float s_in [64 * 64];
    __shared__ __align__(16) float s_mid[64 * 64];
    __shared__ float w1[9], w2[9], bb1, bb2;
    int plane = blockIdx.x;              // b*DI + c
    int c = plane % DI;
    int tid = threadIdx.x;
    if (tid < 9)        w1[tid]     = cw1[c * 9 + tid];
    else if (tid < 18)  w2[tid - 9] = cw2[c * 9 + tid - 9];
    else if (tid == 18) bb1 = cb1[c];
    else if (tid == 19) bb2 = cb2[c];

    const float4* src = (const float4*)(g_x1 + (size_t)plane * LL);
    float4* s4 = (float4*)s_in;
#pragma unroll
    for (int i = 0; i < 4; i++) s4[tid + 256 * i] = src[tid + 256 * i];
    __syncthreads();

    int w = tid & 63, q = tid >> 6;
    float* dst1 = g_xs + (size_t)plane * LT + CC;
    int wl = (w > 0) ? -1 : 0, wr = (w < 63) ? 1 : 0;
#pragma unroll 4
    for (int r = 0; r < 16; r++) {
        int h = q * 16 + r;
        float s = bb1;
#pragma unroll
        for (int kh = 0; kh < 3; kh++) {
            int ih = h + kh - 1;
            if (ih < 0 || ih >= 64) continue;
            const float* row = s_in + ih * 64 + w;
            float acc = w1[kh * 3 + 1] * row[0];
            if (wl) acc += w1[kh * 3 + 0] * row[-1];
            if (wr) acc += w1[kh * 3 + 2] * row[1];
            s += acc;
        }
        float v = silu_f(s);
        s_mid[h * 64 + w] = v;
        dst1[h * 64 + w] = v;
    }
    __syncthreads();

    int ow = tid & 31;
    int oq = tid >> 5;
    float* dst2 = g_dxc + (size_t)plane * 1024;
#pragma unroll
    for (int r = 0; r < 4; r++) {
        int oh = oq * 4 + r;
        float s = bb2;
#pragma unroll
        for (int kh = 0; kh < 3; kh++) {
            int ih = 2 * oh + kh - 1;
            if (ih < 0 || ih >= 64) continue;
#pragma unroll
            for (int kw = 0; kw < 3; kw++) {
                int iw = 2 * ow + kw - 1;
                if (iw < 0 || iw >= 64) continue;
                s += w2[kh * 3 + kw] * s_mid[ih * 64 + iw];
            }
        }
        dst2[oh * 32 + ow] = s;
    }
}

// ---------------- K4a: depth_fc K-split GEMM partials ----------------
// grid = (m_tiles=24, ksplit=16), 192 threads. Block: 16 m x 192 d x 64 k.
// partial[ks][m][d] += X[m][k] * W[d][k]
__global__ void __launch_bounds__(192) k4a_fc(const float* __restrict__ wfc) {
    __shared__ __align__(16) float sXt[KCHUNK * 20];    // [k][m] padded
    __shared__ __align__(16) float sWt[16 * 196];       // [k][d] padded
    int m0 = blockIdx.x * MTILE;         // row = b*DI + lp (0..383)
    int ks = blockIdx.y;
    int k0 = ks * KCHUNK;
    int tid = threadIdx.x;
    int dq = tid % 48, mq = tid / 48;    // thread = 4d x 4m

    // load X tile transposed: 16 m x 64 k -> sXt[k][m]
    for (int i = tid; i < MTILE * (KCHUNK / 4); i += 192) {
        int m = i >> 4, c4 = i & 15;     // c4: k-quad
        float4 v = *(const float4*)(g_dxc + (size_t)(m0 + m) * 1024 + k0 + c4 * 4);
        sXt[(c4 * 4 + 0) * 20 + m] = v.x;
        sXt[(c4 * 4 + 1) * 20 + m] = v.y;
        sXt[(c4 * 4 + 2) * 20 + m] = v.z;
        sXt[(c4 * 4 + 3) * 20 + m] = v.w;
    }

    float acc[4][4];
#pragma unroll
    for (int i = 0; i < 4; i++)
#pragma unroll
        for (int j = 0; j < 4; j++) acc[i][j] = 0.f;

#pragma unroll
    for (int s = 0; s < KCHUNK / 16; s++) {
        __syncthreads();
        // load W slice transposed: 192 d x 16 k -> sWt[k][d]
#pragma unroll
        for (int j = 0; j < 4; j++) {
            int qd = tid + 192 * j;      // 768 float4
            int d = qd >> 2, c = qd & 3; // c: k-quad within slice
            float4 v = *(const float4*)(wfc + (size_t)d * 1024 + k0 + s * 16 + c * 4);
            sWt[(c * 4 + 0) * 196 + d] = v.x;
            sWt[(c * 4 + 1) * 196 + d] = v.y;
            sWt[(c * 4 + 2) * 196 + d] = v.z;
            sWt[(c * 4 + 3) * 196 + d] = v.w;
        }
        __syncthreads();
#pragma unroll
        for (int k = 0; k < 16; k++) {
            float4 w4 = *(const float4*)&sWt[k * 196 + dq * 4];
            float4 x4 = *(const float4*)&sXt[(s * 16 + k) * 20 + mq * 4];
            acc[0][0] += x4.x * w4.x; acc[0][1] += x4.x * w4.y; acc[0][2] += x4.x * w4.z; acc[0][3] += x4.x * w4.w;
            acc[1][0] += x4.y * w4.x; acc[1][1] += x4.y * w4.y; acc[1][2] += x4.y * w4.z; acc[1][3] += x4.y * w4.w;
            acc[2][0] += x4.z * w4.x; acc[2][1] += x4.z * w4.y; acc[2][2] += x4.z * w4.z; acc[2][3] += x4.z * w4.w;
            acc[3][0] += x4.w * w4.x; acc[3][1] += x4.w * w4.y; acc[3][2] += x4.w * w4.z; acc[3][3] += x4.w * w4.w;
        }
    }

    float* pb = g_fcp + ((size_t)ks * BB * DI + m0 + mq * 4) * DI + dq * 4;
#pragma unroll
    for (int m = 0; m < 4; m++) {
        *(float4*)(pb + (size_t)m * DI) =
            make_float4(acc[m][0], acc[m][1], acc[m][2], acc[m][3]);
    }
}

// ---------------- K4b: reduce partials + bias + SiLU -> g_xs (transposed) ----------------
__global__ void __launch_bounds__(192) k4b_fc(const float* __restrict__ fcb) {
    int m = blockIdx.x;                  // b*DI + lp
    int d = threadIdx.x;
    int b = m / DI, lp = m % DI;
    float s = fcb[d];
    const float* p = g_fcp + (size_t)m * DI + d;
#pragma unroll
    for (int ks = 0; ks < KSPLIT; ks++) {
        s += p[(size_t)ks * BB * DI * DI];
    }
    g_xs[((size_t)b * DI + d) * LT + lp] = silu_f(s);
}

// ---------------- K5: x_proj + dt proj + softplus precompute (tiled) ----------------
__global__ void __launch_bounds__(256) k5_xproj(const float* __restrict__ xpw,
                                                const float* __restrict__ dtw,
                                                const float* __restrict__ dtb,
                                                const float* __restrict__ dsv) {
    __shared__ __align__(16) float s_xp[38 * 193];
    __shared__ __align__(16) float sxd[38 * 36];
    __shared__ __align__(16) float s_dtw[DI * RK];
    __shared__ float s_dtb[DI];
    __shared__ float s_ds[DI];
    int tid = threadIdx.x;
    int b   = blockIdx.y;
    int l0  = blockIdx.x * 32;

    for (int i = tid; i < 38 * DI; i += 256) s_xp[(i / DI) * 193 + (i % DI)] = xpw[i];
    for (int i = tid; i < DI * RK; i += 256) s_dtw[i] = dtw[i];
    for (int i = tid; i < DI; i += 256) { s_dtb[i] = dtb[i]; s_ds[i] = dsv[i]; }
    __syncthreads();

    const float* ub = g_xs + (size_t)b * DI * LT + l0;
    for (int item = tid; item < 38 * 8; item += 256) {
        int c = item >> 3, lq = item & 7;
        float4 acc = make_float4(0.f, 0.f, 0.f, 0.f);
        const float* xr = s_xp + c * 193;
#pragma unroll 4
        for (int d = 0; d < DI; d++) {
            float xp = xr[d];
            float4 uv = *(const float4*)(ub + (size_t)d * LT + lq * 4);
            acc.x += xp * uv.x; acc.y += xp * uv.y;
            acc.z += xp * uv.z; acc.w += xp * uv.w;
        }
        *(float4*)&sxd[c * 36 + lq * 4] = acc;
    }
    __syncthreads();

    {
        int n = tid & 15;
        int lh = tid >> 4;
#pragma unroll
        for (int rr = 0; rr < 2; rr++) {
            int l = lh + rr * 16;
            g_bc[((size_t)b * LT + l0 + l) * DSN + n] =
                make_float2(sxd[(RK + n) * 36 + l], sxd[(RK + DSN + n) * 36 + l]);
        }
    }

    const float L2E = 1.4426950408889634f;
    for (int item = tid; item < DI * 8; item += 256) {
        int d = item >> 3, lq = item & 7;
        float dt0 = s_dtb[d], dt1 = dt0, dt2 = dt0, dt3 = dt0;
#pragma unroll
        for (int r = 0; r < RK; r++) {
            float w = s_dtw[d * RK + r];
            float4 xv = *(const float4*)&sxd[r * 36 + lq * 4];
            dt0 += w * xv.x; dt1 += w * xv.y; dt2 += w * xv.z; dt3 += w * xv.w;
        }
        float del[4]; float dts[4] = {dt0, dt1, dt2, dt3};
#pragma unroll
        for (int j = 0; j < 4; j++) {
            float dt = dts[j];
            if (dt > 20.f)       del[j] = dt;
            else if (dt < -20.f) del[j] = __expf(dt);
            else                 del[j] = log1pf(__expf(dt));
        }
        float4 uv = *(const float4*)(ub + (size_t)d * LT + lq * 4);
        float2* qd = g_q2 + ((size_t)b * DI + d) * LT + l0 + lq * 4;
        *(float4*)qd       = make_float4(del[0] * L2E, del[0] * uv.x, del[1] * L2E, del[1] * uv.y);
        *(float4*)(qd + 2) = make_float4(del[2] * L2E, del[2] * uv.z, del[3] * L2E, del[3] * uv.w);
    }
}

// ---------------- K6: chunked selective scan (2 states per thread) ----------------
__global__ void __launch_bounds__(128) k6_phaseA() {
    int W    = blockIdx.x * 4 + (threadIdx.x >> 5);
    int lane = threadIdx.x & 31;
    int grp  = W >> 5;
    int c    = W & 31;
    int half = lane >> 4;
    int n    = lane & 15;
    int b  = grp / 48, dq = grp % 48;
    int d_a = dq * 4 + half, d_b = d_a + 2;
    int g_a = b * DI + d_a, g_b = b * DI + d_b;
    float An_a = g_An[d_a * DSN + n];
    float An_b = g_An[d_b * DSN + n];
    const float2* qa = g_q2 + (size_t)g_a * LT;
    const float2* qb = g_q2 + (size_t)g_b * LT;
    const float2* bc = g_bc + (size_t)b * LT * DSN;
    float ha = 0.f, Pa = 1.f, hb = 0.f, Pb = 1.f;
    int l0 = c * CL;
#pragma unroll 2
    for (int l = l0; l < l0 + CL; l++) {
        float2 q1 = qa[l];
        float2 q2v = qb[l];
        float2 bv = bc[(size_t)l * DSN + n];
        float aa = ex2(q1.x * An_a);
        float ab = ex2(q2v.x * An_b);
        Pa *= aa; ha = aa * ha + q1.y * bv.x;
        Pb *= ab; hb = ab * hb + q2v.y * bv.x;
    }
    int ia = (g_a * NC + c) * DSN + n;
    int ib = (g_b * NC + c) * DSN + n;
    g_hend[ia] = ha; g_P[ia] = Pa;
    g_hend[ib] = hb; g_P[ib] = Pb;
}

__global__ void k6_phaseB() {
    int t = blockIdx.x * blockDim.x + threadIdx.x;
    if (t >= BB * DI * DSN) return;
    int n = t & 15;
    int g = t >> 4;
    float h = 0.f;
    for (int c = 0; c < NC; c++) {
        int idx = (g * NC + c) * DSN + n;
        g_h0[idx] = h;
        h = g_P[idx] * h + g_hend[idx];
    }
}

__global__ void __launch_bounds__(128) k6_phaseC(const float* __restrict__ dsv) {
    int W    = blockIdx.x * 4 + (threadIdx.x >> 5);
    int lane = threadIdx.x & 31;
    int grp  = W >> 5;
    int c    = W & 31;
    int half = lane >> 4;
    int n    = lane & 15;
    int b  = grp / 48, dq = grp % 48;
    int d_a = dq * 4 + half, d_b = d_a + 2;
    int g_a = b * DI + d_a, g_b = b * DI + d_b;
    float An_a = g_An[d_a * DSN + n];
    float An_b = g_An[d_b * DSN + n];
    float ds_a = dsv[d_a], ds_b = dsv[d_b];
    const float2* qa = g_q2 + (size_t)g_a * LT;
    const float2* qb = g_q2 + (size_t)g_b * LT;
    const float*  ua = g_xs + (size_t)g_a * LT;
    const float*  ub = g_xs + (size_t)g_b * LT;
    const float2* bc = g_bc + (size_t)b * LT * DSN;
    float ha = g_h0[(g_a * NC + c) * DSN + n];
    float hb = g_h0[(g_b * NC + c) * DSN + n];
    int l0 = c * CL;
#pragma unroll 2
    for (int l = l0; l < l0 + CL; l++) {
        float2 q1 = qa[l];
        float2 q2v = qb[l];
        float2 bv = bc[(size_t)l * DSN + n];
        float aa = ex2(q1.x * An_a);
        float ab = ex2(q2v.x * An_b);
        ha = aa * ha + q1.y * bv.x;
        hb = ab * hb + q2v.y * bv.x;
        float pa = ha * bv.y;
        float pb = hb * bv.y;
        pa += __shfl_xor_sync(0xffffffffu, pa, 1);
        pb += __shfl_xor_sync(0xffffffffu, pb, 1);
        pa += __shfl_xor_sync(0xffffffffu, pa, 2);
        pb += __shfl_xor_sync(0xffffffffu, pb, 2);
        pa += __shfl_xor_sync(0xffffffffu, pa, 4);
        pb += __shfl_xor_sync(0xffffffffu, pb, 4);
        pa += __shfl_xor_sync(0xffffffffu, pa, 8);
        pb += __shfl_xor_sync(0xffffffffu, pb, 8);
        if (n == 0 && l >= CC) {
            float* yo = g_yt + ((size_t)b * LL + (l - CC)) * DI;
            yo[d_a] = pa + ds_a * ua[l];
            yo[d_b] = pb + ds_b * ub[l];
        }
    }
}

// ---------------- K7: LayerNorm + SiLU(z) gate + out_proj (8 l per block) ----------------
__global__ void __launch_bounds__(192) k7_out(const float* __restrict__ onw,
                                              const float* __restrict__ onb,
                                              float* __restrict__ out) {
    __shared__ __align__(16) float sy [8 * DI];
    __shared__ __align__(16) float sgv[8 * DI];
    __shared__ __align__(16) float sred[8 * DM];
    __shared__ float smu[8], srs[8];
    int b   = blockIdx.y;
    int l0  = blockIdx.x * 8;
    int tid = threadIdx.x;
    int lane = tid & 31, w = tid >> 5;

    const float4* ysrc = (const float4*)(g_yt + ((size_t)b * LL + l0) * DI);
    float4* syd = (float4*)sy;
#pragma unroll
    for (int i = 0; i < 2; i++) syd[tid + 192 * i] = ysrc[tid + 192 * i];
    __syncthreads();

#pragma unroll
    for (int pass = 0; pass < 2; pass++) {
        int l = pass * 6 + w;
        if (l < 8) {
            float s1 = 0.f, s2 = 0.f;
#pragma unroll
            for (int k = 0; k < 6; k++) {
                float v = sy[l * DI + lane + 32 * k];
                s1 += v; s2 += v * v;
            }
#pragma unroll
            for (int o = 16; o > 0; o >>= 1) {
                s1 += __shfl_xor_sync(0xffffffffu, s1, o);
                s2 += __shfl_xor_sync(0xffffffffu, s2, o);
            }
            if (lane == 0) {
                float mu = s1 * (1.f / 192.f);
                smu[l] = mu;
                srs[l] = rsqrtf(s2 * (1.f / 192.f) - mu * mu + 1e-5f);
            }
        }
    }
    __syncthreads();

    float wn = onw[tid], bn = onb[tid];
    const float* zr = g_z + ((size_t)b * LL + l0) * DI + tid;
#pragma unroll
    for (int l = 0; l < 8; l++) {
        float y  = sy[l * DI + tid];
        float yn = (y - smu[l]) * srs[l] * wn + bn;
        float zv = zr[(size_t)l * DI];
        sgv[l * DI + tid] = yn * silu_f(zv);
    }
    __syncthreads();

    int o = tid % DM, half = tid / DM, d0 = half * DM;
    float acc[8];
#pragma unroll
    for (int l = 0; l < 8; l++) acc[l] = 0.f;
    const float* wp = g_wtO + (size_t)d0 * DM + o;
#pragma unroll 4
    for (int i = 0; i < 96; i++) {
        float wv = wp[(size_t)i * DM];
        const float* gv = sgv + d0 + i;
#pragma unroll
        for (int l = 0; l < 8; l++) acc[l] += gv[l * DI] * wv;
    }
    if (half == 0) {
#pragma unroll
        for (int l = 0; l < 8; l++) sred[l * DM + o] = acc[l];
    }
    __syncthreads();
    if (half == 1) {
        float* op = out + ((size_t)b * LL + l0) * DM + o;
#pragma unroll
        for (int l = 0; l < 8; l++) op[(size_t)l * DM] = acc[l] + sred[l * DM + o];
    }
}

// ---------------- launch ----------------
extern "C" void kernel_launch(void* const* d_in, const int* in_sizes, int n_in,
                              void* d_out, int out_size) {
    const float* x            = (const float*)d_in[0];
    const float* in_proj_w    = (const float*)d_in[1];
    const float* conv2d_w     = (const float*)d_in[2];
    const float* conv2d_b     = (const float*)d_in[3];
    const float* depth_conv_w = (const float*)d_in[4];
    const float* depth_conv_b = (const float*)d_in[5];
    const float* depth_fc_w   = (const float*)d_in[6];
    const float* depth_fc_b   = (const float*)d_in[7];
    const float* x_proj_w     = (const float*)d_in[8];
    const float* dt_projs_w   = (const float*)d_in[9];
    const float* dt_projs_b   = (const float*)d_in[10];
    const float* A_logs       = (const float*)d_in[11];
    const float* Ds           = (const float*)d_in[12];
    const float* out_norm_w   = (const float*)d_in[13];
    const float* out_norm_b   = (const float*)d_in[14];
    const float* out_proj_w   = (const float*)d_in[15];
    float* out = (float*)d_out;

    k0_prep<<<(2 * DI * DM + 255) / 256, 256>>>(in_proj_w, out_proj_w, A_logs);
    k1_inproj<<<dim3(LL / 32, BB), 384>>>(x);
    k23_conv<<<BB * DI, 256>>>(conv2d_w, conv2d_b, depth_conv_w, depth_conv_b);
    k4a_fc<<<dim3(BB * DI / MTILE, KSPLIT), 192>>>(depth_fc_w);
    k4b_fc<<<BB * DI, 192>>>(depth_fc_b);
    k5_xproj<<<dim3(LT / 32, BB), 256>>>(x_proj_w, dt_projs_w, dt_projs_b, Ds);
    k6_phaseA<<<768, 128>>>();
    k6_phaseB<<<24, 256>>>();
    k6_phaseC<<<768, 128>>>(Ds);
    k7_out<<<dim3(LL / 8, BB), 192>>>(out_norm_w, out_norm_b, out);
}

// round 6
// speedup vs baseline: 1.3088x; 1.1415x over previous
#include <cuda_runtime.h>
#include <math.h>

#define DM 96
#define DI 192
#define DSN 16
#define RK 6
#define BB 2
#define LL 4096
#define CC 192
#define LT 4288
#define NC 32
#define CL 134
#define KSPLIT 16
#define KCHUNK 64
#define MTILE 16

// ---------------- static scratch (no allocs allowed) ----------------
__device__ __align__(16) float  g_wtA[DM * 2 * DI];   // in_proj_w transposed: [k][j] 96x384
__device__ __align__(16) float  g_wtO[DI * DM];       // out_proj_w transposed: [d][o] 192x96
__device__ __align__(16) float  g_An [DI * DSN];      // -exp(A_logs)
__device__ __align__(16) float  g_x1 [BB * DI * LL];  // conv input  (b,c,h,w)
__device__ __align__(16) float  g_xs [BB * DI * LT];  // u = xs      (b,d,ltot)
__device__ __align__(16) float  g_z  [BB * LL * DI];  // z           (b,l,d)
__device__ __align__(16) float  g_dxc[BB * DI * 1024];// stride-2 conv out (b,c,1024)
__device__ __align__(16) float  g_fcp[KSPLIT * BB * DI * DI]; // depth_fc partials [ks][m][d]
__device__ __align__(16) float2 g_bc [BB * LT * DSN]; // (B_n, C_n)  (b,l,n)
__device__ __align__(16) float2 g_q2 [BB * DI * LT];  // (delta*log2e, delta*u)
__device__ __align__(16) float  g_yt [BB * LL * DI];  // scan y (b,l,d)
__device__ __align__(16) float  g_hend[BB * DI * NC * DSN];
__device__ __align__(16) float  g_P   [BB * DI * NC * DSN];

__device__ __forceinline__ float ex2(float x) {
    float r; asm("ex2.approx.ftz.f32 %0, %1;" : "=f"(r) : "f"(x)); return r;
}
__device__ __forceinline__ float silu_f(float v) {
    return __fdividef(v, 1.f + __expf(-v));
}

// ---------------- K0: weight transposes + A table ----------------
__global__ void k0_prep(const float* __restrict__ ipw, const float* __restrict__ opw,
                        const float* __restrict__ alogs) {
    int t = blockIdx.x * blockDim.x + threadIdx.x;
    if (t < 2 * DI * DM) {
        int j = t / DM, k = t % DM;
        g_wtA[k * (2 * DI) + j] = ipw[t];
    }
    if (t < DM * DI) {
        int o = t / DI, d = t % DI;
        g_wtO[d * DM + o] = opw[t];
    }
    if (t < DI * DSN) {
        g_An[t] = -expf(alogs[t]);
    }
}

// ---------------- K1: xz = x @ in_proj_w.T ; split x1 (NCHW) / z (b,l,d) ----------------
__global__ void __launch_bounds__(384) k1_inproj(const float* __restrict__ x) {
    __shared__ __align__(16) float xt[96 * 36];
    __shared__ __align__(16) float zs[32 * DI];
    int b  = blockIdx.y;
    int l0 = blockIdx.x * 32;
    int tid = threadIdx.x;

    const float4* xin = (const float4*)(x + ((size_t)b * LL + l0) * DM);
    for (int i = tid; i < 32 * 24; i += 384) {
        float4 v = xin[i];
        int l = i / 24, k4 = (i % 24) * 4;
        xt[(k4 + 0) * 36 + l] = v.x;
        xt[(k4 + 1) * 36 + l] = v.y;
        xt[(k4 + 2) * 36 + l] = v.z;
        xt[(k4 + 3) * 36 + l] = v.w;
    }
    __syncthreads();

    int j = tid;
    float acc[32];
#pragma unroll
    for (int l = 0; l < 32; l++) acc[l] = 0.f;
    for (int k = 0; k < 96; k++) {
        float w = g_wtA[k * 384 + j];
#pragma unroll
        for (int l4 = 0; l4 < 8; l4++) {
            float4 xv = *(const float4*)&xt[k * 36 + l4 * 4];
            acc[l4 * 4 + 0] += xv.x * w;
            acc[l4 * 4 + 1] += xv.y * w;
            acc[l4 * 4 + 2] += xv.z * w;
            acc[l4 * 4 + 3] += xv.w * w;
        }
    }
    if (j < DI) {
        float* dst = g_x1 + ((size_t)b * DI + j) * LL + l0;
#pragma unroll
        for (int l4 = 0; l4 < 8; l4++) {
            *(float4*)(dst + l4 * 4) =
                make_float4(acc[l4*4], acc[l4*4+1], acc[l4*4+2], acc[l4*4+3]);
        }
    } else {
        int d = j - DI;
#pragma unroll
        for (int l = 0; l < 32; l++) zs[l * DI + d] = acc[l];
    }
    __syncthreads();
    float4* zdst = (float4*)(g_z + ((size_t)b * LL + l0) * DI);
    const float4* zsrc = (const float4*)zs;
    for (int i = tid; i < 32 * 48; i += 384) zdst[i] = zsrc[i];
}

// ---------------- K23: fused depthwise conv s1+SiLU and conv s2 (smem-resident) ----------------
__global__ void __launch_bounds__(256) k23_conv(const float* __restrict__ cw1,
                                                const float* __restrict__ cb1,
                                                const float* __restrict__ cw2,
                                                const float* __restrict__ cb2) {
    __shared__ __align__(16) float s_in [64 * 64];
    __shared__ __align__(16) float s_mid[64 * 64];
    __shared__ float w1[9], w2[9], bb1, bb2;
    int plane = blockIdx.x;              // b*DI + c
    int c = plane % DI;
    int tid = threadIdx.x;
    if (tid < 9)        w1[tid]     = cw1[c * 9 + tid];
    else if (tid < 18)  w2[tid - 9] = cw2[c * 9 + tid - 9];
    else if (tid == 18) bb1 = cb1[c];
    else if (tid == 19) bb2 = cb2[c];

    const float4* src = (const float4*)(g_x1 + (size_t)plane * LL);
    float4* s4 = (float4*)s_in;
#pragma unroll
    for (int i = 0; i < 4; i++) s4[tid + 256 * i] = src[tid + 256 * i];
    __syncthreads();

    int w = tid & 63, q = tid >> 6;
    float* dst1 = g_xs + (size_t)plane * LT + CC;
    int wl = (w > 0) ? -1 : 0, wr = (w < 63) ? 1 : 0;
#pragma unroll 4
    for (int r = 0; r < 16; r++) {
        int h = q * 16 + r;
        float s = bb1;
#pragma unroll
        for (int kh = 0; kh < 3; kh++) {
            int ih = h + kh - 1;
            if (ih < 0 || ih >= 64) continue;
            const float* row = s_in + ih * 64 + w;
            float acc = w1[kh * 3 + 1] * row[0];
            if (wl) acc += w1[kh * 3 + 0] * row[-1];
            if (wr) acc += w1[kh * 3 + 2] * row[1];
            s += acc;
        }
        float v = silu_f(s);
        s_mid[h * 64 + w] = v;
        dst1[h * 64 + w] = v;
    }
    __syncthreads();

    int ow = tid & 31;
    int oq = tid >> 5;
    float* dst2 = g_dxc + (size_t)plane * 1024;
#pragma unroll
    for (int r = 0; r < 4; r++) {
        int oh = oq * 4 + r;
        float s = bb2;
#pragma unroll
        for (int kh = 0; kh < 3; kh++) {
            int ih = 2 * oh + kh - 1;
            if (ih < 0 || ih >= 64) continue;
#pragma unroll
            for (int kw = 0; kw < 3; kw++) {
                int iw = 2 * ow + kw - 1;
                if (iw < 0 || iw >= 64) continue;
                s += w2[kh * 3 + kw] * s_mid[ih * 64 + iw];
            }
        }
        dst2[oh * 32 + ow] = s;
    }
}

// ---------------- K4a: depth_fc K-split GEMM partials ----------------
__global__ void __launch_bounds__(192) k4a_fc(const float* __restrict__ wfc) {
    __shared__ __align__(16) float sXt[KCHUNK * 20];    // [k][m] padded
    __shared__ __align__(16) float sWt[16 * 196];       // [k][d] padded
    int m0 = blockIdx.x * MTILE;
    int ks = blockIdx.y;
    int k0 = ks * KCHUNK;
    int tid = threadIdx.x;
    int dq = tid % 48, mq = tid / 48;

    for (int i = tid; i < MTILE * (KCHUNK / 4); i += 192) {
        int m = i >> 4, c4 = i & 15;
        float4 v = *(const float4*)(g_dxc + (size_t)(m0 + m) * 1024 + k0 + c4 * 4);
        sXt[(c4 * 4 + 0) * 20 + m] = v.x;
        sXt[(c4 * 4 + 1) * 20 + m] = v.y;
        sXt[(c4 * 4 + 2) * 20 + m] = v.z;
        sXt[(c4 * 4 + 3) * 20 + m] = v.w;
    }

    float acc[4][4];
#pragma unroll
    for (int i = 0; i < 4; i++)
#pragma unroll
        for (int j = 0; j < 4; j++) acc[i][j] = 0.f;

#pragma unroll
    for (int s = 0; s < KCHUNK / 16; s++) {
        __syncthreads();
#pragma unroll
        for (int j = 0; j < 4; j++) {
            int qd = tid + 192 * j;
            int d = qd >> 2, c = qd & 3;
            float4 v = *(const float4*)(wfc + (size_t)d * 1024 + k0 + s * 16 + c * 4);
            sWt[(c * 4 + 0) * 196 + d] = v.x;
            sWt[(c * 4 + 1) * 196 + d] = v.y;
            sWt[(c * 4 + 2) * 196 + d] = v.z;
            sWt[(c * 4 + 3) * 196 + d] = v.w;
        }
        __syncthreads();
#pragma unroll
        for (int k = 0; k < 16; k++) {
            float4 w4 = *(const float4*)&sWt[k * 196 + dq * 4];
            float4 x4 = *(const float4*)&sXt[(s * 16 + k) * 20 + mq * 4];
            acc[0][0] += x4.x * w4.x; acc[0][1] += x4.x * w4.y; acc[0][2] += x4.x * w4.z; acc[0][3] += x4.x * w4.w;
            acc[1][0] += x4.y * w4.x; acc[1][1] += x4.y * w4.y; acc[1][2] += x4.y * w4.z; acc[1][3] += x4.y * w4.w;
            acc[2][0] += x4.z * w4.x; acc[2][1] += x4.z * w4.y; acc[2][2] += x4.z * w4.z; acc[2][3] += x4.z * w4.w;
            acc[3][0] += x4.w * w4.x; acc[3][1] += x4.w * w4.y; acc[3][2] += x4.w * w4.z; acc[3][3] += x4.w * w4.w;
        }
    }

    float* pb = g_fcp + ((size_t)ks * BB * DI + m0 + mq * 4) * DI + dq * 4;
#pragma unroll
    for (int m = 0; m < 4; m++) {
        *(float4*)(pb + (size_t)m * DI) =
            make_float4(acc[m][0], acc[m][1], acc[m][2], acc[m][3]);
    }
}

// ---------------- K4b: reduce partials + bias + SiLU -> g_xs (transposed) ----------------
__global__ void __launch_bounds__(192) k4b_fc(const float* __restrict__ fcb) {
    int m = blockIdx.x;
    int d = threadIdx.x;
    int b = m / DI, lp = m % DI;
    float s = fcb[d];
    const float* p = g_fcp + (size_t)m * DI + d;
#pragma unroll
    for (int ks = 0; ks < KSPLIT; ks++) {
        s += p[(size_t)ks * BB * DI * DI];
    }
    g_xs[((size_t)b * DI + d) * LT + lp] = silu_f(s);
}

// ---------------- K5: x_proj + dt proj + softplus precompute (tiled) ----------------
__global__ void __launch_bounds__(256) k5_xproj(const float* __restrict__ xpw,
                                                const float* __restrict__ dtw,
                                                const float* __restrict__ dtb,
                                                const float* __restrict__ dsv) {
    __shared__ __align__(16) float s_xp[38 * 193];
    __shared__ __align__(16) float sxd[38 * 36];
    __shared__ __align__(16) float s_dtw[DI * RK];
    __shared__ float s_dtb[DI];
    __shared__ float s_ds[DI];
    int tid = threadIdx.x;
    int b   = blockIdx.y;
    int l0  = blockIdx.x * 32;

    for (int i = tid; i < 38 * DI; i += 256) s_xp[(i / DI) * 193 + (i % DI)] = xpw[i];
    for (int i = tid; i < DI * RK; i += 256) s_dtw[i] = dtw[i];
    for (int i = tid; i < DI; i += 256) { s_dtb[i] = dtb[i]; s_ds[i] = dsv[i]; }
    __syncthreads();

    const float* ub = g_xs + (size_t)b * DI * LT + l0;
    for (int item = tid; item < 38 * 8; item += 256) {
        int c = item >> 3, lq = item & 7;
        float4 acc = make_float4(0.f, 0.f, 0.f, 0.f);
        const float* xr = s_xp + c * 193;
#pragma unroll 4
        for (int d = 0; d < DI; d++) {
            float xp = xr[d];
            float4 uv = *(const float4*)(ub + (size_t)d * LT + lq * 4);
            acc.x += xp * uv.x; acc.y += xp * uv.y;
            acc.z += xp * uv.z; acc.w += xp * uv.w;
        }
        *(float4*)&sxd[c * 36 + lq * 4] = acc;
    }
    __syncthreads();

    {
        int n = tid & 15;
        int lh = tid >> 4;
#pragma unroll
        for (int rr = 0; rr < 2; rr++) {
            int l = lh + rr * 16;
            g_bc[((size_t)b * LT + l0 + l) * DSN + n] =
                make_float2(sxd[(RK + n) * 36 + l], sxd[(RK + DSN + n) * 36 + l]);
        }
    }

    const float L2E = 1.4426950408889634f;
    for (int item = tid; item < DI * 8; item += 256) {
        int d = item >> 3, lq = item & 7;
        float dt0 = s_dtb[d], dt1 = dt0, dt2 = dt0, dt3 = dt0;
#pragma unroll
        for (int r = 0; r < RK; r++) {
            float w = s_dtw[d * RK + r];
            float4 xv = *(const float4*)&sxd[r * 36 + lq * 4];
            dt0 += w * xv.x; dt1 += w * xv.y; dt2 += w * xv.z; dt3 += w * xv.w;
        }
        float del[4]; float dts[4] = {dt0, dt1, dt2, dt3};
#pragma unroll
        for (int j = 0; j < 4; j++) {
            float dt = dts[j];
            if (dt > 20.f)       del[j] = dt;
            else if (dt < -20.f) del[j] = __expf(dt);
            else                 del[j] = log1pf(__expf(dt));
        }
        float4 uv = *(const float4*)(ub + (size_t)d * LT + lq * 4);
        float2* qd = g_q2 + ((size_t)b * DI + d) * LT + l0 + lq * 4;
        *(float4*)qd       = make_float4(del[0] * L2E, del[0] * uv.x, del[1] * L2E, del[1] * uv.y);
        *(float4*)(qd + 2) = make_float4(del[2] * L2E, del[2] * uv.z, del[3] * L2E, del[3] * uv.w);
    }
}

// ---------------- K6: smem-staged chunked selective scan ----------------
// block = (b, chunk c, 16-d group). 256 threads = 8 warps; warp w covers d = dg*16 + w*2 + half.
__global__ void __launch_bounds__(256) k6_phaseA() {
    __shared__ __align__(16) float2 s_q[16][CL];     // [d][l]
    __shared__ __align__(16) float2 s_bc[CL][DSN];   // [l][n]
    int dg = blockIdx.x % 12;
    int c  = blockIdx.x / 12;
    int b  = blockIdx.y;
    int t  = threadIdx.x;
    int l0 = c * CL;

    {   // stage q rows: 16 threads per d-row, coalesced 128B
        int dl = t >> 4, j = t & 15;
        const float2* src = g_q2 + (size_t)(b * DI + dg * 16 + dl) * LT + l0;
        for (int k = j; k < CL; k += 16) s_q[dl][k] = src[k];
    }
    {   // stage bc tile: contiguous float4
        const float4* src = (const float4*)(g_bc + ((size_t)b * LT + l0) * DSN);
        float4* dst = (float4*)&s_bc[0][0];
        for (int i = t; i < CL * DSN / 2; i += 256) dst[i] = src[i];
    }
    __syncthreads();

    int lane = t & 31, w = t >> 5;
    int half = lane >> 4, n = lane & 15;
    int dw = w * 2 + half;
    int d  = dg * 16 + dw;
    int g  = b * DI + d;
    float An = g_An[d * DSN + n];
    float h = 0.f, P = 1.f;
#pragma unroll 2
    for (int l = 0; l < CL; l++) {
        float2 qq = s_q[dw][l];
        float2 bv = s_bc[l][n];
        float a = ex2(qq.x * An);
        P *= a;
        h = a * h + qq.y * bv.x;
    }
    int idx = (g * NC + c) * DSN + n;
    g_hend[idx] = h;
    g_P[idx]    = P;
}

__global__ void __launch_bounds__(256) k6_phaseC(const float* __restrict__ dsv) {
    __shared__ __align__(16) float2 s_q[16][CL];     // [d][l]
    __shared__ __align__(16) float2 s_bc[CL][DSN];   // [l][n]
    __shared__ __align__(16) float  s_y[CL][16];     // [l][d] (init = Ds*u)
    int dg = blockIdx.x % 12;
    int c  = blockIdx.x / 12;
    int b  = blockIdx.y;
    int t  = threadIdx.x;
    int l0 = c * CL;

    {   // stage q rows + y init (Ds*u)
        int dl = t >> 4, j = t & 15;
        int gq = b * DI + dg * 16 + dl;
        const float2* src = g_q2 + (size_t)gq * LT + l0;
        for (int k = j; k < CL; k += 16) s_q[dl][k] = src[k];
        float ds = dsv[dg * 16 + dl];
        const float* us = g_xs + (size_t)gq * LT + l0;
        for (int k = j; k < CL; k += 16) s_y[k][dl] = ds * us[k];
    }
    {   // stage bc tile
        const float4* src = (const float4*)(g_bc + ((size_t)b * LT + l0) * DSN);
        float4* dst = (float4*)&s_bc[0][0];
        for (int i = t; i < CL * DSN / 2; i += 256) dst[i] = src[i];
    }

    int lane = t & 31, w = t >> 5;
    int half = lane >> 4, n = lane & 15;
    int dw = w * 2 + half;
    int d  = dg * 16 + dw;
    int g  = b * DI + d;

    // folded phaseB: per-thread prefix over chunks 0..c-1 (L2-resident arrays)
    float h = 0.f;
    for (int cc = 0; cc < c; cc++) {
        int idx = (g * NC + cc) * DSN + n;
        h = g_P[idx] * h + g_hend[idx];
    }
    float An = g_An[d * DSN + n];
    __syncthreads();

    for (int l = 0; l < CL; l++) {
        float2 qq = s_q[dw][l];
        float2 bv = s_bc[l][n];
        float a = ex2(qq.x * An);
        h = a * h + qq.y * bv.x;
        float pr = h * bv.y;
        pr += __shfl_xor_sync(0xffffffffu, pr, 1);
        pr += __shfl_xor_sync(0xffffffffu, pr, 2);
        pr += __shfl_xor_sync(0xffffffffu, pr, 4);
        pr += __shfl_xor_sync(0xffffffffu, pr, 8);
        if (n == 0) s_y[l][dw] += pr;
    }
    __syncthreads();

    // write y rows (lg >= CC), coalesced float4
    for (int i = t; i < CL * 4; i += 256) {
        int l = i >> 2, q4 = i & 3;
        int lg = l0 + l;
        if (lg >= CC) {
            float4 v = *(const float4*)&s_y[l][q4 * 4];
            *(float4*)(g_yt + ((size_t)b * LL + (lg - CC)) * DI + dg * 16 + q4 * 4) = v;
        }
    }
}

// ---------------- K7: LayerNorm + SiLU(z) gate + out_proj (8 l per block) ----------------
__global__ void __launch_bounds__(192) k7_out(const float* __restrict__ onw,
                                              const float* __restrict__ onb,
                                              float* __restrict__ out) {
    __shared__ __align__(16) float sy [8 * DI];
    __shared__ __align__(16) float sgv[8 * DI];
    __shared__ __align__(16) float sred[8 * DM];
    __shared__ float smu[8], srs[8];
    int b   = blockIdx.y;
    int l0  = blockIdx.x * 8;
    int tid = threadIdx.x;
    int lane = tid & 31, w = tid >> 5;

    const float4* ysrc = (const float4*)(g_yt + ((size_t)b * LL + l0) * DI);
    float4* syd = (float4*)sy;
#pragma unroll
    for (int i = 0; i < 2; i++) syd[tid + 192 * i] = ysrc[tid + 192 * i];
    __syncthreads();

#pragma unroll
    for (int pass = 0; pass < 2; pass++) {
        int l = pass * 6 + w;
        if (l < 8) {
            float s1 = 0.f, s2 = 0.f;
#pragma unroll
            for (int k = 0; k < 6; k++) {
                float v = sy[l * DI + lane + 32 * k];
                s1 += v; s2 += v * v;
            }
#pragma unroll
            for (int o = 16; o > 0; o >>= 1) {
                s1 += __shfl_xor_sync(0xffffffffu, s1, o);
                s2 += __shfl_xor_sync(0xffffffffu, s2, o);
            }
            if (lane == 0) {
                float mu = s1 * (1.f / 192.f);
                smu[l] = mu;
                srs[l] = rsqrtf(s2 * (1.f / 192.f) - mu * mu + 1e-5f);
            }
        }
    }
    __syncthreads();

    float wn = onw[tid], bn = onb[tid];
    const float* zr = g_z + ((size_t)b * LL + l0) * DI + tid;
#pragma unroll
    for (int l = 0; l < 8; l++) {
        float y  = sy[l * DI + tid];
        float yn = (y - smu[l]) * srs[l] * wn + bn;
        float zv = zr[(size_t)l * DI];
        sgv[l * DI + tid] = yn * silu_f(zv);
    }
    __syncthreads();

    int o = tid % DM, half = tid / DM, d0 = half * DM;
    float acc[8];
#pragma unroll
    for (int l = 0; l < 8; l++) acc[l] = 0.f;
    const float* wp = g_wtO + (size_t)d0 * DM + o;
#pragma unroll 4
    for (int i = 0; i < 96; i++) {
        float wv = wp[(size_t)i * DM];
        const float* gv = sgv + d0 + i;
#pragma unroll
        for (int l = 0; l < 8; l++) acc[l] += gv[l * DI] * wv;
    }
    if (half == 0) {
#pragma unroll
        for (int l = 0; l < 8; l++) sred[l * DM + o] = acc[l];
    }
    __syncthreads();
    if (half == 1) {
        float* op = out + ((size_t)b * LL + l0) * DM + o;
#pragma unroll
        for (int l = 0; l < 8; l++) op[(size_t)l * DM] = acc[l] + sred[l * DM + o];
    }
}

// ---------------- launch ----------------
extern "C" void kernel_launch(void* const* d_in, const int* in_sizes, int n_in,
                              void* d_out, int out_size) {
    const float* x            = (const float*)d_in[0];
    const float* in_proj_w    = (const float*)d_in[1];
    const float* conv2d_w     = (const float*)d_in[2];
    const float* conv2d_b     = (const float*)d_in[3];
    const float* depth_conv_w = (const float*)d_in[4];
    const float* depth_conv_b = (const float*)d_in[5];
    const float* depth_fc_w   = (const float*)d_in[6];
    const float* depth_fc_b   = (const float*)d_in[7];
    const float* x_proj_w     = (const float*)d_in[8];
    const float* dt_projs_w   = (const float*)d_in[9];
    const float* dt_projs_b   = (const float*)d_in[10];
    const float* A_logs       = (const float*)d_in[11];
    const float* Ds           = (const float*)d_in[12];
    const float* out_norm_w   = (const float*)d_in[13];
    const float* out_norm_b   = (const float*)d_in[14];
    const float* out_proj_w   = (const float*)d_in[15];
    float* out = (float*)d_out;

    k0_prep<<<(2 * DI * DM + 255) / 256, 256>>>(in_proj_w, out_proj_w, A_logs);
    k1_inproj<<<dim3(LL / 32, BB), 384>>>(x);
    k23_conv<<<BB * DI, 256>>>(conv2d_w, conv2d_b, depth_conv_w, depth_conv_b);
    k4a_fc<<<dim3(BB * DI / MTILE, KSPLIT), 192>>>(depth_fc_w);
    k4b_fc<<<BB * DI, 192>>>(depth_fc_b);
    k5_xproj<<<dim3(LT / 32, BB), 256>>>(x_proj_w, dt_projs_w, dt_projs_b, Ds);
    k6_phaseA<<<dim3(12 * NC, BB), 256>>>();
    k6_phaseC<<<dim3(12 * NC, BB), 256>>>(Ds);
    k7_out<<<dim3(LL / 8, BB), 192>>>(out_norm_w, out_norm_b, out);
}